// round 7
// baseline (speedup 1.0000x reference)
#include <cuda_runtime.h>

// Problem dims
#define U_LEN 2048
#define R_LEN 256
#define L_LEN 1024
#define M_LEN 512
#define D_DIM 1024
#define NHEAD 16
#define HDIM  64
#define QLEN  (U_LEN + R_LEN)                   // 2304
#define KVLEN (M_LEN + R_LEN + L_LEN + U_LEN)   // 3840
#define MR    (M_LEN + R_LEN)                   // 768
#define KVIN  (MR + U_LEN)                      // 2816

// ---------------- packed tile geometry ----------------
// GEMM A tile: 128 rows x 16 k, packed as [64 rowpairs][36 words]
//   word(r,c) = rp(r)*36 + cpi(c)*4 + 2*qtr(c) + half(r)
//   rp = (r/32)*16 + ((r%32)/16)*8 + (r%8); half = (r%16)/8
//   cpi = (c/8)*4 + (c%4); qtr = (c%8)/4
#define ATILE_W 2304     // 64*36 words
#define ATILE_B 9216
// GEMM B tile: 128 rows x 16 k, packed as [128 rows][24 words]
//   word(row,c) = row*24 + ((c/8)*4 + c%4)*2 + (c%8)/4
#define BTILE_W 3072
#define BTILE_B 12288
#define NKT     (D_DIM / 16)   // 64 k-tiles

// Attention K: per head [3840 rows][72 words], col-pair packed
//   word(j,c) = j*72 + ((c/8)*4 + c%4)*2 + (c%8)/4
#define KROW_W   72
#define KTILE_W  (64 * KROW_W)       // 4608
#define KHEAD_W  (KVLEN * KROW_W)    // 276480
// Attention V: per head, per 64-row tile [32 rowpairs][144 words]
//   word(j,c) = (j/64 tile)*4608 + ((j%64)/8*4 + (j%8)%4)*144 + 2*c + ((j%8)/4)
#define VTILE_W  4608
#define VHEAD_W  (KVLEN / 64 * VTILE_W)  // 276480

// Scratch (no cudaMalloc allowed)
__device__ unsigned g_kvin_blk[22 * 64 * ATILE_W];
__device__ unsigned g_attn_blk[18 * 64 * ATILE_W];
__device__ unsigned g_Wq_blk  [ 8 * 64 * BTILE_W];
__device__ unsigned g_Wkv_blk [16 * 64 * BTILE_W];
__device__ unsigned g_Wo_blk  [ 8 * 64 * BTILE_W];
__device__ unsigned g_query_t [QLEN * D_DIM];     // pre-scaled tf32 query, row-major
__device__ float    g_key_hs  [NHEAD * KHEAD_W];
__device__ float    g_val_hs  [NHEAD * VHEAD_W];

// ---------------------------------------------------------------------------
// helpers
// ---------------------------------------------------------------------------
__device__ __forceinline__ unsigned f2tf32(float f) {
    unsigned r;
    asm("cvt.rna.tf32.f32 %0, %1;" : "=r"(r) : "f"(f));
    return r;
}

__device__ __forceinline__ void mma_tf32(float* d, const unsigned* a, unsigned b0, unsigned b1) {
    asm volatile(
        "mma.sync.aligned.m16n8k8.row.col.f32.tf32.tf32.f32 "
        "{%0,%1,%2,%3}, {%4,%5,%6,%7}, {%8,%9}, {%0,%1,%2,%3};"
        : "+f"(d[0]), "+f"(d[1]), "+f"(d[2]), "+f"(d[3])
        : "r"(a[0]), "r"(a[1]), "r"(a[2]), "r"(a[3]), "r"(b0), "r"(b1));
}

__device__ __forceinline__ unsigned smaddr(const void* p) {
    return (unsigned)__cvta_generic_to_shared(p);
}
__device__ __forceinline__ void mbar_init(unsigned a) {
    asm volatile("mbarrier.init.shared.b64 [%0], 1;" :: "r"(a) : "memory");
}
__device__ __forceinline__ void mbar_expect(unsigned a, unsigned tx) {
    asm volatile("mbarrier.arrive.expect_tx.shared.b64 _, [%0], %1;" :: "r"(a), "r"(tx) : "memory");
}
__device__ __forceinline__ void bulk_g2s(unsigned sdst, const void* gsrc, unsigned bytes, unsigned mbar) {
    asm volatile("cp.async.bulk.shared::cta.global.mbarrier::complete_tx::bytes [%0], [%1], %2, [%3];"
                 :: "r"(sdst), "l"(gsrc), "r"(bytes), "r"(mbar) : "memory");
}
__device__ __forceinline__ void mbar_wait(unsigned a, unsigned ph) {
    asm volatile(
        "{\n\t.reg .pred P;\n\t"
        "WL%=:\n\t"
        "mbarrier.try_wait.parity.acquire.cta.shared::cta.b64 P, [%0], %1, 0x989680;\n\t"
        "@P bra WD%=;\n\t"
        "bra WL%=;\n\t"
        "WD%=:\n\t}"
        :: "r"(a), "r"(ph) : "memory");
}

// packed-layout index helpers
__device__ __forceinline__ int a_rp(int r)   { return (r >> 5) * 16 + ((r & 31) >> 4) * 8 + (r & 7); }
__device__ __forceinline__ int a_half(int r) { return (r >> 3) & 1; }
__device__ __forceinline__ int pk_fpi(int c) { return ((c >> 3) << 2) + (c & 3); }
__device__ __forceinline__ int pk_qtr(int c) { return (c >> 2) & 1; }

// ---------------------------------------------------------------------------
// Prepass: weights -> packed B tiles
// ---------------------------------------------------------------------------
__global__ void conv_w_blk(const float* __restrict__ src, unsigned* __restrict__ dst, int n4)
{
    int i = blockIdx.x * blockDim.x + threadIdx.x;
    for (; i < n4; i += gridDim.x * blockDim.x) {
        int row = i >> 8;                  // K = 1024 -> 256 float4 per row
        int col = (i & 255) * 4;
        float4 v = ((const float4*)src)[i];
        int blk = row >> 7, kt = col >> 4, r = row & 127, c0 = col & 15;
        unsigned* base = dst + ((size_t)(blk * 64 + kt)) * BTILE_W + r * 24 + pk_qtr(c0);
        int f0 = (c0 >> 3) * 4;
        base[(f0 + 0) * 2] = f2tf32(v.x);
        base[(f0 + 1) * 2] = f2tf32(v.y);
        base[(f0 + 2) * 2] = f2tf32(v.z);
        base[(f0 + 3) * 2] = f2tf32(v.w);
    }
}

// Prepass: gather concat(mem, rctx, utter) -> packed A tiles
__global__ void conv_kvin_blk(const float* __restrict__ utter,
                              const float* __restrict__ rctx,
                              const float* __restrict__ mem)
{
    int i = blockIdx.x * blockDim.x + threadIdx.x;
    const int n4 = KVIN * D_DIM / 4;
    for (; i < n4; i += gridDim.x * blockDim.x) {
        int row = i >> 8;
        int col = (i & 255) * 4;
        const float4* s = (row < M_LEN)
            ? (const float4*)(mem + (size_t)row * D_DIM + col)
            : (row < MR)
            ? (const float4*)(rctx + (size_t)(row - M_LEN) * D_DIM + col)
            : (const float4*)(utter + (size_t)(row - MR) * D_DIM + col);
        float4 v = *s;
        int blk = row >> 7, kt = col >> 4, r = row & 127, c0 = col & 15;
        unsigned* base = g_kvin_blk + ((size_t)(blk * 64 + kt)) * ATILE_W
                       + a_rp(r) * 36 + 2 * pk_qtr(c0) + a_half(r);
        int f0 = (c0 >> 3) * 4;
        base[(f0 + 0) * 4] = f2tf32(v.x);
        base[(f0 + 1) * 4] = f2tf32(v.y);
        base[(f0 + 2) * 4] = f2tf32(v.z);
        base[(f0 + 3) * 4] = f2tf32(v.w);
    }
}

// Prepass: left-context rows into packed head-major K/V
__global__ void conv_lc(const float* __restrict__ lck, const float* __restrict__ lcv)
{
    int i = blockIdx.x * blockDim.x + threadIdx.x;
    const int n4 = L_LEN * D_DIM / 4;
    for (; i < n4; i += gridDim.x * blockDim.x) {
        int row = i >> 8;              // 0..1023
        int col = (i & 255) * 4;       // 0..1020
        int head = col >> 6, c = col & 63;
        int krow = MR + row;
        float4 k4 = *(const float4*)(lck + (size_t)row * D_DIM + col);
        float4 v4 = *(const float4*)(lcv + (size_t)row * D_DIM + col);
        // K
        {
            float* base = g_key_hs + (size_t)head * KHEAD_W + (size_t)krow * KROW_W + pk_qtr(c);
            int f0 = (c >> 3) * 4;
            base[(f0 + 0) * 2] = k4.x;
            base[(f0 + 1) * 2] = k4.y;
            base[(f0 + 2) * 2] = k4.z;
            base[(f0 + 3) * 2] = k4.w;
        }
        // V
        {
            int tile = krow >> 6, j = krow & 63;
            int rp = ((j >> 3) << 2) + (j & 3);
            int half = (j >> 2) & 1;
            float* base = g_val_hs + (size_t)head * VHEAD_W + (size_t)tile * VTILE_W
                        + rp * 144 + 2 * c + half;
            base[0] = v4.x; base[2] = v4.y; base[4] = v4.z; base[6] = v4.w;
        }
    }
}

// ---------------------------------------------------------------------------
// TF32 GEMM, packed operands + bulk-copy pipeline.
// BM=BN=128, BK=16, 256 threads (8 warps 4x2), 3-stage mbarrier pipeline.
// MODE 0: A=kvin blocks 4..21 (q_in) -> g_query_t (tf32 pre-scaled)
// MODE 1: A=kvin blocks 0..21        -> key/value fp32 + packed head-major K/V
// MODE 2: A=g_attn_blk               -> out fp32
// ---------------------------------------------------------------------------
#define GEMM_SMEM ((3 * ATILE_W + 3 * BTILE_W) * 4 + 32)

template <int MODE>
__global__ __launch_bounds__(256, 2)
void gemm_blk(const float* __restrict__ bias,
              float* __restrict__ C0,
              float* __restrict__ C1)
{
    extern __shared__ unsigned gsm[];
    unsigned* As = gsm;                    // [3][2304]
    unsigned* Bs = gsm + 3 * ATILE_W;      // [3][3072]
    const unsigned mb0 = smaddr(gsm + 3 * ATILE_W + 3 * BTILE_W);

    const int tid  = threadIdx.x;
    const int lane = tid & 31;
    const int warp = tid >> 5;
    const int wr   = warp & 3;
    const int wc   = warp >> 2;
    const int bm = blockIdx.y, bn = blockIdx.x;
    const int tig = lane & 3, grp = lane >> 2;

    const unsigned* Ab =
        (MODE == 0) ? g_kvin_blk + (size_t)(bm + 4) * 64 * ATILE_W
      : (MODE == 1) ? g_kvin_blk + (size_t)bm * 64 * ATILE_W
                    : g_attn_blk + (size_t)bm * 64 * ATILE_W;
    const unsigned* Wb =
        ((MODE == 0) ? g_Wq_blk : (MODE == 1) ? g_Wkv_blk : g_Wo_blk)
        + (size_t)bn * 64 * BTILE_W;

    if (tid == 0) {
        mbar_init(mb0); mbar_init(mb0 + 8); mbar_init(mb0 + 16);
    }
    __syncthreads();
    if (tid == 0) {
#pragma unroll
        for (int s = 0; s < 3; s++) {
            mbar_expect(mb0 + 8 * s, ATILE_B + BTILE_B);
            bulk_g2s(smaddr(As + s * ATILE_W), Ab + (size_t)s * ATILE_W, ATILE_B, mb0 + 8 * s);
            bulk_g2s(smaddr(Bs + s * BTILE_W), Wb + (size_t)s * BTILE_W, BTILE_B, mb0 + 8 * s);
        }
    }

    float acc[2][8][4];
#pragma unroll
    for (int mt = 0; mt < 2; mt++)
#pragma unroll
        for (int nt = 0; nt < 8; nt++)
#pragma unroll
            for (int i = 0; i < 4; i++) acc[mt][nt][i] = 0.f;

    for (int kt = 0; kt < NKT; kt++) {
        const int s = kt % 3;
        const unsigned ph = (unsigned)((kt / 3) & 1);
        mbar_wait(mb0 + 8 * s, ph);

        const unsigned* Asl = As + s * ATILE_W;
        const unsigned* Bsl = Bs + s * BTILE_W;
#pragma unroll
        for (int ks = 0; ks < 2; ks++) {
            unsigned b[8][2];
#pragma unroll
            for (int nt = 0; nt < 8; nt++) {
                int brow = wc * 64 + nt * 8 + grp;
                uint2 bb = *(const uint2*)(Bsl + brow * 24 + (ks * 4 + tig) * 2);
                b[nt][0] = bb.x; b[nt][1] = bb.y;
            }
#pragma unroll
            for (int mt = 0; mt < 2; mt++) {
                int rp0 = wr * 16 + mt * 8 + grp;
                uint4 av = *(const uint4*)(Asl + rp0 * 36 + (ks * 4 + tig) * 4);
                unsigned a[4] = {av.x, av.y, av.z, av.w};
#pragma unroll
                for (int nt = 0; nt < 8; nt++) mma_tf32(acc[mt][nt], a, b[nt][0], b[nt][1]);
            }
        }
        __syncthreads();
        if (tid == 0 && kt + 3 < NKT) {
            mbar_expect(mb0 + 8 * s, ATILE_B + BTILE_B);
            bulk_g2s(smaddr(As + s * ATILE_W), Ab + (size_t)(kt + 3) * ATILE_W, ATILE_B, mb0 + 8 * s);
            bulk_g2s(smaddr(Bs + s * BTILE_W), Wb + (size_t)(kt + 3) * BTILE_W, BTILE_B, mb0 + 8 * s);
        }
    }

    // epilogue
#pragma unroll
    for (int mt = 0; mt < 2; mt++) {
#pragma unroll
        for (int nt = 0; nt < 8; nt++) {
            int col = bn * 128 + wc * 64 + nt * 8 + 2 * tig;
#pragma unroll
            for (int half = 0; half < 2; half++) {
                int row = bm * 128 + wr * 32 + mt * 16 + grp + half * 8;
                float v0 = acc[mt][nt][half * 2 + 0] + bias[col];
                float v1 = acc[mt][nt][half * 2 + 1] + bias[col + 1];
                if (MODE == 0) {
                    uint2 o = make_uint2(f2tf32(v0 * 0.125f), f2tf32(v1 * 0.125f));
                    *(uint2*)(g_query_t + (size_t)row * D_DIM + col) = o;
                } else if (MODE == 1) {
                    int krow = (row < MR) ? row : row + L_LEN;
                    if (col < D_DIM) {
                        *(float2*)(C0 + (size_t)krow * D_DIM + col) = make_float2(v0, v1);
                        int head = col >> 6, c = col & 63;
                        float* base = g_key_hs + (size_t)head * KHEAD_W
                                    + (size_t)krow * KROW_W + pk_qtr(c);
                        int f0 = pk_fpi(c);
                        base[f0 * 2] = v0;
                        base[(f0 + 1) * 2] = v1;
                    } else {
                        int vc = col - D_DIM;
                        *(float2*)(C1 + (size_t)krow * D_DIM + vc) = make_float2(v0, v1);
                        int head = vc >> 6, c = vc & 63;
                        int tile = krow >> 6, j = krow & 63;
                        int rp = ((j >> 3) << 2) + (j & 3);
                        int vh = (j >> 2) & 1;
                        float* base = g_val_hs + (size_t)head * VHEAD_W + (size_t)tile * VTILE_W
                                    + rp * 144 + 2 * c + vh;
                        base[0] = v0; base[2] = v1;
                    }
                } else {
                    *(float2*)(C0 + (size_t)row * D_DIM + col) = make_float2(v0, v1);
                }
            }
        }
    }
}

// ---------------------------------------------------------------------------
// Tensor-core flash attention, 512 threads = 256 q rows of one head.
// Packed K/V tiles (64 keys) via single cp.async.bulk each, 3-stage pipeline.
// ---------------------------------------------------------------------------
#define AT_NT   (KVLEN / 64)    // 60
#define PS_STR  72
#define ATT_SMEM ((3 * KTILE_W + 3 * VTILE_W + 16 * 16 * PS_STR) * 4 + 32)

__global__ __launch_bounds__(512, 1)
void attn_mma(int dummy)
{
    extern __shared__ float sm[];
    float* Ks = sm;                               // [3][4608]
    float* Vs = sm + 3 * KTILE_W;                 // [3][4608]
    float* Pa = sm + 3 * KTILE_W + 3 * VTILE_W;   // [16][16*72]
    const unsigned mb0 = smaddr(Pa + 16 * 16 * PS_STR);

    const int h   = blockIdx.x;
    const int qb  = blockIdx.y;
    const int tid = threadIdx.x;
    const int lane = tid & 31;
    const int w    = tid >> 5;
    const int grp  = lane >> 2;
    const int tig  = lane & 3;
    float* Pw = Pa + w * 16 * PS_STR;

    const float* ksrc = g_key_hs + (size_t)h * KHEAD_W;
    const float* vsrc = g_val_hs + (size_t)h * VHEAD_W;

    if (tid == 0) {
        mbar_init(mb0); mbar_init(mb0 + 8); mbar_init(mb0 + 16);
    }
    __syncthreads();
    if (tid == 0) {
#pragma unroll
        for (int s = 0; s < 3; s++) {
            mbar_expect(mb0 + 8 * s, (KTILE_W + VTILE_W) * 4);
            bulk_g2s(smaddr(Ks + s * KTILE_W), ksrc + (size_t)s * KTILE_W, KTILE_W * 4, mb0 + 8 * s);
            bulk_g2s(smaddr(Vs + s * VTILE_W), vsrc + (size_t)s * VTILE_W, VTILE_W * 4, mb0 + 8 * s);
        }
    }

    // Q fragments (pre-scaled tf32)
    unsigned qa[8][4];
    {
        const unsigned* q0 = g_query_t + (size_t)(qb * 256 + w * 16 + grp) * D_DIM + h * HDIM;
        const unsigned* q1 = q0 + 8 * D_DIM;
#pragma unroll
        for (int kb = 0; kb < 8; kb++) {
            qa[kb][0] = q0[kb * 8 + tig];
            qa[kb][1] = q1[kb * 8 + tig];
            qa[kb][2] = q0[kb * 8 + tig + 4];
            qa[kb][3] = q1[kb * 8 + tig + 4];
        }
    }

    float acc[8][4];
#pragma unroll
    for (int nt = 0; nt < 8; nt++)
#pragma unroll
        for (int i = 0; i < 4; i++) acc[nt][i] = 0.f;
    float m0 = -1e30f, m1 = -1e30f, l0 = 0.f, l1 = 0.f;

    for (int t = 0; t < AT_NT; t++) {
        const int s = t % 3;
        const unsigned ph = (unsigned)((t / 3) & 1);
        mbar_wait(mb0 + 8 * s, ph);

        const float* Kc = Ks + s * KTILE_W;
        const float* Vc = Vs + s * VTILE_W;

        // ---- S = Q K^T ----
        float sc[8][4];
#pragma unroll
        for (int nt = 0; nt < 8; nt++)
#pragma unroll
            for (int i = 0; i < 4; i++) sc[nt][i] = 0.f;
#pragma unroll
        for (int kb = 0; kb < 8; kb++) {
#pragma unroll
            for (int nt = 0; nt < 8; nt++) {
                uint2 bb = *(const uint2*)(Kc + (nt * 8 + grp) * KROW_W + (kb * 4 + tig) * 2);
                mma_tf32(sc[nt], qa[kb], bb.x, bb.y);
            }
        }

        // ---- online softmax ----
        float mt0 = -1e30f, mt1 = -1e30f;
#pragma unroll
        for (int nt = 0; nt < 8; nt++) {
            mt0 = fmaxf(mt0, fmaxf(sc[nt][0], sc[nt][1]));
            mt1 = fmaxf(mt1, fmaxf(sc[nt][2], sc[nt][3]));
        }
        mt0 = fmaxf(mt0, __shfl_xor_sync(0xffffffff, mt0, 1));
        mt0 = fmaxf(mt0, __shfl_xor_sync(0xffffffff, mt0, 2));
        mt1 = fmaxf(mt1, __shfl_xor_sync(0xffffffff, mt1, 1));
        mt1 = fmaxf(mt1, __shfl_xor_sync(0xffffffff, mt1, 2));

        float mn0 = fmaxf(m0, mt0), mn1 = fmaxf(m1, mt1);
        float c0 = __expf(m0 - mn0), c1 = __expf(m1 - mn1);
        l0 *= c0; l1 *= c1;
        m0 = mn0; m1 = mn1;

#pragma unroll
        for (int nt = 0; nt < 8; nt++) {
            float p00 = __expf(sc[nt][0] - mn0);
            float p01 = __expf(sc[nt][1] - mn0);
            float p10 = __expf(sc[nt][2] - mn1);
            float p11 = __expf(sc[nt][3] - mn1);
            l0 += p00 + p01;
            l1 += p10 + p11;
            *(float2*)&Pw[grp * PS_STR + nt * 8 + 2 * tig]       = make_float2(p00, p01);
            *(float2*)&Pw[(grp + 8) * PS_STR + nt * 8 + 2 * tig] = make_float2(p10, p11);
            acc[nt][0] *= c0; acc[nt][1] *= c0;
            acc[nt][2] *= c1; acc[nt][3] *= c1;
        }
        __syncwarp();

        // ---- acc += P @ V ----
#pragma unroll
        for (int kb = 0; kb < 8; kb++) {
            unsigned a[4];
            a[0] = __float_as_uint(Pw[grp * PS_STR + kb * 8 + tig]);
            a[1] = __float_as_uint(Pw[(grp + 8) * PS_STR + kb * 8 + tig]);
            a[2] = __float_as_uint(Pw[grp * PS_STR + kb * 8 + tig + 4]);
            a[3] = __float_as_uint(Pw[(grp + 8) * PS_STR + kb * 8 + tig + 4]);
#pragma unroll
            for (int nt = 0; nt < 8; nt++) {
                uint2 bb = *(const uint2*)(Vc + (kb * 4 + tig) * 144 + 2 * (nt * 8 + grp));
                mma_tf32(acc[nt], a, bb.x, bb.y);
            }
        }

        __syncthreads();
        if (tid == 0 && t + 3 < AT_NT) {
            mbar_expect(mb0 + 8 * s, (KTILE_W + VTILE_W) * 4);
            bulk_g2s(smaddr(Ks + s * KTILE_W), ksrc + (size_t)(t + 3) * KTILE_W, KTILE_W * 4, mb0 + 8 * s);
            bulk_g2s(smaddr(Vs + s * VTILE_W), vsrc + (size_t)(t + 3) * VTILE_W, VTILE_W * 4, mb0 + 8 * s);
        }
    }

    // ---- finalize: write packed A-tile layout for gemm2 ----
    l0 += __shfl_xor_sync(0xffffffff, l0, 1);
    l0 += __shfl_xor_sync(0xffffffff, l0, 2);
    l1 += __shfl_xor_sync(0xffffffff, l1, 1);
    l1 += __shfl_xor_sync(0xffffffff, l1, 2);
    float inv0 = 1.f / l0, inv1 = 1.f / l1;

    int rbase = qb * 256 + w * 16 + grp;
#pragma unroll
    for (int half = 0; half < 2; half++) {
        int r = rbase + half * 8;
        int blk = r >> 7, rr = r & 127;
        int rp = a_rp(rr), hf = a_half(rr);
        float inv = half ? inv1 : inv0;
#pragma unroll
        for (int nt = 0; nt < 8; nt++) {
            int col = h * HDIM + nt * 8 + 2 * tig;
            int kt = col >> 4, c16 = col & 15;
            unsigned* base = g_attn_blk + ((size_t)(blk * 64 + kt)) * ATILE_W
                           + rp * 36 + 2 * pk_qtr(c16) + hf;
            int f0 = pk_fpi(c16);
            base[f0 * 4]       = f2tf32(acc[nt][half * 2 + 0] * inv);
            base[(f0 + 1) * 4] = f2tf32(acc[nt][half * 2 + 1] * inv);
        }
    }
}

// ---------------------------------------------------------------------------
extern "C" void kernel_launch(void* const* d_in, const int* in_sizes, int n_in,
                              void* d_out, int out_size)
{
    const float* utter = (const float*)d_in[0];
    const float* rctx  = (const float*)d_in[1];
    const float* mem   = (const float*)d_in[2];
    const float* lck   = (const float*)d_in[3];
    const float* lcv   = (const float*)d_in[4];
    const float* Wq    = (const float*)d_in[5];
    const float* bq    = (const float*)d_in[6];
    const float* Wkv   = (const float*)d_in[7];
    const float* bkv   = (const float*)d_in[8];
    const float* Wo    = (const float*)d_in[9];
    const float* bo    = (const float*)d_in[10];

    float* out = (float*)d_out;                       // [2304, 1024]
    float* key = out + (size_t)QLEN * D_DIM;          // [3840, 1024]
    float* val = key + (size_t)KVLEN * D_DIM;         // [3840, 1024]

    static bool attr_done = false;
    if (!attr_done) {
        cudaFuncSetAttribute(attn_mma, cudaFuncAttributeMaxDynamicSharedMemorySize, ATT_SMEM);
        cudaFuncSetAttribute(gemm_blk<0>, cudaFuncAttributeMaxDynamicSharedMemorySize, GEMM_SMEM);
        cudaFuncSetAttribute(gemm_blk<1>, cudaFuncAttributeMaxDynamicSharedMemorySize, GEMM_SMEM);
        cudaFuncSetAttribute(gemm_blk<2>, cudaFuncAttributeMaxDynamicSharedMemorySize, GEMM_SMEM);
        attr_done = true;
    }

    unsigned *wq_b, *wkv_b, *wo_b;
    cudaGetSymbolAddress((void**)&wq_b,  g_Wq_blk);
    cudaGetSymbolAddress((void**)&wkv_b, g_Wkv_blk);
    cudaGetSymbolAddress((void**)&wo_b,  g_Wo_blk);

    // 0) prepass conversions
    conv_w_blk<<<256, 256>>>(Wq,  wq_b,  D_DIM * D_DIM / 4);
    conv_w_blk<<<512, 256>>>(Wkv, wkv_b, 2 * D_DIM * D_DIM / 4);
    conv_w_blk<<<256, 256>>>(Wo,  wo_b,  D_DIM * D_DIM / 4);
    conv_kvin_blk<<<512, 256>>>(utter, rctx, mem);
    conv_lc<<<256, 256>>>(lck, lcv);

    // 1) query projection -> g_query_t (pre-scaled tf32)
    gemm_blk<0><<<dim3(D_DIM / 128, QLEN / 128), 256, GEMM_SMEM>>>(bq, nullptr, nullptr);

    // 2) kv projection -> key/value (fp32) + packed head-major K/V
    gemm_blk<1><<<dim3(2 * D_DIM / 128, KVIN / 128), 256, GEMM_SMEM>>>(bkv, key, val);

    // 3) left-context splice into d_out (contiguous)
    cudaMemcpyAsync(key + (size_t)MR * D_DIM, lck,
                    (size_t)L_LEN * D_DIM * sizeof(float),
                    cudaMemcpyDeviceToDevice, 0);
    cudaMemcpyAsync(val + (size_t)MR * D_DIM, lcv,
                    (size_t)L_LEN * D_DIM * sizeof(float),
                    cudaMemcpyDeviceToDevice, 0);

    // 4) attention -> g_attn_blk (packed tf32)
    attn_mma<<<dim3(NHEAD, QLEN / 256), 512, ATT_SMEM>>>(0);

    // 5) output projection
    gemm_blk<2><<<dim3(D_DIM / 128, QLEN / 128), 256, GEMM_SMEM>>>(bo, out, nullptr);
}

// round 8
// speedup vs baseline: 1.2164x; 1.2164x over previous
#include <cuda_runtime.h>

// Problem dims
#define U_LEN 2048
#define R_LEN 256
#define L_LEN 1024
#define M_LEN 512
#define D_DIM 1024
#define NHEAD 16
#define HDIM  64
#define QLEN  (U_LEN + R_LEN)                   // 2304
#define KVLEN (M_LEN + R_LEN + L_LEN + U_LEN)   // 3840
#define MR    (M_LEN + R_LEN)                   // 768
#define KVIN  (MR + U_LEN)                      // 2816

// blocked tile: 128 rows x 16 k (+4 pad) = 2560 words = 10240 B
#define BLKW   2560
#define TILEB  10240
#define NKT    (D_DIM / 16)      // 64 k-tiles

// head-major padded K/V
#define KHS_STR 68
#define VHS_STR 72
#define KHS_HEAD (KVLEN * KHS_STR)   // 261120
#define VHS_HEAD (KVLEN * VHS_STR)   // 276480

// log2(e) folded into q scaling: scores arrive in log2 domain
#define QSCALE (0.125f * 1.4426950408889634f)

// Scratch (no cudaMalloc allowed)
__device__ unsigned g_kvin_blk[22 * 64 * BLKW];
__device__ unsigned g_Wq_blk  [ 8 * 64 * BLKW];
__device__ unsigned g_Wkv_blk [16 * 64 * BLKW];
__device__ unsigned g_Wo_blk  [ 8 * 64 * BLKW];
__device__ unsigned g_attn_blk[18 * 64 * BLKW];
__device__ unsigned g_query_t [QLEN * D_DIM];        // pre-scaled tf32 query
__device__ float    g_key_hs  [NHEAD * KHS_HEAD];    // head-major padded K
__device__ float    g_val_hs  [NHEAD * VHS_HEAD];    // head-major padded V

// ---------------------------------------------------------------------------
// helpers
// ---------------------------------------------------------------------------
__device__ __forceinline__ unsigned f2tf32(float f) {
    unsigned r;
    asm("cvt.rna.tf32.f32 %0, %1;" : "=r"(r) : "f"(f));
    return r;
}

__device__ __forceinline__ void mma_tf32(float* d, const unsigned* a, unsigned b0, unsigned b1) {
    asm volatile(
        "mma.sync.aligned.m16n8k8.row.col.f32.tf32.tf32.f32 "
        "{%0,%1,%2,%3}, {%4,%5,%6,%7}, {%8,%9}, {%0,%1,%2,%3};"
        : "+f"(d[0]), "+f"(d[1]), "+f"(d[2]), "+f"(d[3])
        : "r"(a[0]), "r"(a[1]), "r"(a[2]), "r"(a[3]), "r"(b0), "r"(b1));
}

__device__ __forceinline__ unsigned smaddr(const void* p) {
    return (unsigned)__cvta_generic_to_shared(p);
}
__device__ __forceinline__ void mbar_init(unsigned a) {
    asm volatile("mbarrier.init.shared.b64 [%0], 1;" :: "r"(a) : "memory");
}
__device__ __forceinline__ void mbar_expect(unsigned a, unsigned tx) {
    asm volatile("mbarrier.arrive.expect_tx.shared.b64 _, [%0], %1;" :: "r"(a), "r"(tx) : "memory");
}
__device__ __forceinline__ void bulk_g2s(unsigned sdst, const void* gsrc, unsigned bytes, unsigned mbar) {
    asm volatile("cp.async.bulk.shared::cta.global.mbarrier::complete_tx::bytes [%0], [%1], %2, [%3];"
                 :: "r"(sdst), "l"(gsrc), "r"(bytes), "r"(mbar) : "memory");
}
__device__ __forceinline__ void mbar_wait(unsigned a, unsigned ph) {
    asm volatile(
        "{\n\t.reg .pred P;\n\t"
        "WL%=:\n\t"
        "mbarrier.try_wait.parity.acquire.cta.shared::cta.b64 P, [%0], %1, 0x989680;\n\t"
        "@P bra WD%=;\n\t"
        "bra WL%=;\n\t"
        "WD%=:\n\t}"
        :: "r"(a), "r"(ph) : "memory");
}

// ---------------------------------------------------------------------------
// Prepass: weights -> blocked tf32 tiles. rows = N, cols = K=1024.
// ---------------------------------------------------------------------------
__global__ void conv_w_blk(const float* __restrict__ src, unsigned* __restrict__ dst, int n4)
{
    int i = blockIdx.x * blockDim.x + threadIdx.x;
    for (; i < n4; i += gridDim.x * blockDim.x) {
        int row = i >> 8;
        int col = (i & 255) * 4;
        float4 v = ((const float4*)src)[i];
        uint4 o;
        o.x = f2tf32(v.x); o.y = f2tf32(v.y); o.z = f2tf32(v.z); o.w = f2tf32(v.w);
        size_t off = ((size_t)(row >> 7) * 64 + (col >> 4)) * BLKW + (row & 127) * 20 + (col & 15);
        *(uint4*)(dst + off) = o;
    }
}

// Prepass: gather concat(mem, rctx, utter) -> blocked tf32
__global__ void conv_kvin_blk(const float* __restrict__ utter,
                              const float* __restrict__ rctx,
                              const float* __restrict__ mem)
{
    int i = blockIdx.x * blockDim.x + threadIdx.x;
    const int n4 = KVIN * D_DIM / 4;
    for (; i < n4; i += gridDim.x * blockDim.x) {
        int row = i >> 8;
        int col = (i & 255) * 4;
        const float4* s = (row < M_LEN)
            ? (const float4*)(mem + (size_t)row * D_DIM + col)
            : (row < MR)
            ? (const float4*)(rctx + (size_t)(row - M_LEN) * D_DIM + col)
            : (const float4*)(utter + (size_t)(row - MR) * D_DIM + col);
        float4 v = *s;
        uint4 o;
        o.x = f2tf32(v.x); o.y = f2tf32(v.y); o.z = f2tf32(v.z); o.w = f2tf32(v.w);
        size_t off = ((size_t)(row >> 7) * 64 + (col >> 4)) * BLKW + (row & 127) * 20 + (col & 15);
        *(uint4*)(g_kvin_blk + off) = o;
    }
}

// Prepass: left-context rows into head-major padded K/V
__global__ void conv_lc(const float* __restrict__ lck, const float* __restrict__ lcv)
{
    int i = blockIdx.x * blockDim.x + threadIdx.x;
    const int n4 = L_LEN * D_DIM / 4;
    for (; i < n4; i += gridDim.x * blockDim.x) {
        int row = i >> 8;
        int col = (i & 255) * 4;
        int head = col >> 6, c = col & 63;
        float4 k4 = *(const float4*)(lck + (size_t)row * D_DIM + col);
        float4 v4 = *(const float4*)(lcv + (size_t)row * D_DIM + col);
        *(float4*)(g_key_hs + (size_t)head * KHS_HEAD + (size_t)(MR + row) * KHS_STR + c) = k4;
        *(float4*)(g_val_hs + (size_t)head * VHS_HEAD + (size_t)(MR + row) * VHS_STR + c) = v4;
    }
}

// ---------------------------------------------------------------------------
// TF32 GEMM with bulk-copy pipeline: C[M,N] = A_blk @ W_blk^T + bias
// BM=BN=128, BK=16, 256 threads (8 warps 4x2).
// 4-stage mbarrier pipeline, ONE syncthreads per 2 k-tiles.
// ---------------------------------------------------------------------------
#define GEMM_SMEM (8 * BLKW * 4 + 64)

template <int MODE>
__global__ __launch_bounds__(256, 2)
void gemm_blk(const float* __restrict__ bias,
              float* __restrict__ C0,
              float* __restrict__ C1)
{
    extern __shared__ unsigned gsm[];
    unsigned* As = gsm;               // [4][2560]
    unsigned* Bs = gsm + 4 * BLKW;    // [4][2560]
    const unsigned mb0 = smaddr(gsm + 8 * BLKW);   // 4 mbarriers

    const int tid  = threadIdx.x;
    const int lane = tid & 31;
    const int warp = tid >> 5;
    const int wr   = warp & 3;
    const int wc   = warp >> 2;
    const int bm = blockIdx.y, bn = blockIdx.x;
    const int tig = lane & 3, grp = lane >> 2;

    const unsigned* Ab =
        (MODE == 0) ? g_kvin_blk + (size_t)(bm + 4) * 64 * BLKW
      : (MODE == 1) ? g_kvin_blk + (size_t)bm * 64 * BLKW
                    : g_attn_blk + (size_t)bm * 64 * BLKW;
    const unsigned* Wb =
        ((MODE == 0) ? g_Wq_blk : (MODE == 1) ? g_Wkv_blk : g_Wo_blk)
        + (size_t)bn * 64 * BLKW;

    if (tid == 0) {
        mbar_init(mb0); mbar_init(mb0 + 8); mbar_init(mb0 + 16); mbar_init(mb0 + 24);
    }
    __syncthreads();
    if (tid == 0) {
#pragma unroll
        for (int s = 0; s < 4; s++) {
            mbar_expect(mb0 + 8 * s, 2 * TILEB);
            bulk_g2s(smaddr(As + s * BLKW), Ab + (size_t)s * BLKW, TILEB, mb0 + 8 * s);
            bulk_g2s(smaddr(Bs + s * BLKW), Wb + (size_t)s * BLKW, TILEB, mb0 + 8 * s);
        }
    }

    float acc[2][8][4];
#pragma unroll
    for (int mt = 0; mt < 2; mt++)
#pragma unroll
        for (int nt = 0; nt < 8; nt++)
#pragma unroll
            for (int i = 0; i < 4; i++) acc[mt][nt][i] = 0.f;

    for (int g = 0; g < NKT / 2; g++) {
#pragma unroll
        for (int sub = 0; sub < 2; sub++) {
            const int kt = 2 * g + sub;
            const int s  = kt & 3;
            mbar_wait(mb0 + 8 * s, (unsigned)((kt >> 2) & 1));

            const unsigned* Asl = As + s * BLKW;
            const unsigned* Bsl = Bs + s * BLKW;
#pragma unroll
            for (int ks = 0; ks < 2; ks++) {
                int kk = ks * 8;
                unsigned b[8][2];
#pragma unroll
                for (int nt = 0; nt < 8; nt++) {
                    int brow = wc * 64 + nt * 8 + grp;
                    b[nt][0] = Bsl[brow * 20 + kk + tig];
                    b[nt][1] = Bsl[brow * 20 + kk + tig + 4];
                }
#pragma unroll
                for (int mt = 0; mt < 2; mt++) {
                    unsigned a[4];
                    int r0 = wr * 32 + mt * 16 + grp;
                    a[0] = Asl[r0 * 20 + kk + tig];       a[1] = Asl[(r0 + 8) * 20 + kk + tig];
                    a[2] = Asl[r0 * 20 + kk + tig + 4];   a[3] = Asl[(r0 + 8) * 20 + kk + tig + 4];
#pragma unroll
                    for (int nt = 0; nt < 8; nt++) mma_tf32(acc[mt][nt], a, b[nt][0], b[nt][1]);
                }
            }
        }
        __syncthreads();
        if (tid == 0 && 2 * g + 4 < NKT) {
#pragma unroll
            for (int sub = 0; sub < 2; sub++) {
                const int kt = 2 * g + 4 + sub;
                const int s  = kt & 3;
                mbar_expect(mb0 + 8 * s, 2 * TILEB);
                bulk_g2s(smaddr(As + s * BLKW), Ab + (size_t)kt * BLKW, TILEB, mb0 + 8 * s);
                bulk_g2s(smaddr(Bs + s * BLKW), Wb + (size_t)kt * BLKW, TILEB, mb0 + 8 * s);
            }
        }
    }

    // epilogue
#pragma unroll
    for (int mt = 0; mt < 2; mt++) {
#pragma unroll
        for (int nt = 0; nt < 8; nt++) {
            int col = bn * 128 + wc * 64 + nt * 8 + 2 * tig;
#pragma unroll
            for (int half = 0; half < 2; half++) {
                int row = bm * 128 + wr * 32 + mt * 16 + grp + half * 8;
                float v0 = acc[mt][nt][half * 2 + 0] + bias[col];
                float v1 = acc[mt][nt][half * 2 + 1] + bias[col + 1];
                if (MODE == 0) {
                    uint2 o = make_uint2(f2tf32(v0 * QSCALE), f2tf32(v1 * QSCALE));
                    *(uint2*)(g_query_t + (size_t)row * D_DIM + col) = o;
                } else if (MODE == 1) {
                    int krow = (row < MR) ? row : row + L_LEN;
                    if (col < D_DIM) {
                        *(float2*)(C0 + (size_t)krow * D_DIM + col) = make_float2(v0, v1);
                        *(float2*)(g_key_hs + (size_t)(col >> 6) * KHS_HEAD
                                   + (size_t)krow * KHS_STR + (col & 63)) = make_float2(v0, v1);
                    } else {
                        int vc = col - D_DIM;
                        *(float2*)(C1 + (size_t)krow * D_DIM + vc) = make_float2(v0, v1);
                        *(float2*)(g_val_hs + (size_t)(vc >> 6) * VHS_HEAD
                                   + (size_t)krow * VHS_STR + (vc & 63)) = make_float2(v0, v1);
                    }
                } else {
                    *(float2*)(C0 + (size_t)row * D_DIM + col) = make_float2(v0, v1);
                }
            }
        }
    }
}

// ---------------------------------------------------------------------------
// Tensor-core flash attention, 512 threads = 256 q rows of one head.
// 4-stage bulk pipeline, ONE syncthreads per 2 tiles (warps free-run inside).
// Softmax in log2 domain (exp2f; 0.125*log2e folded into q).
// ---------------------------------------------------------------------------
#define AT_TK   64
#define AT_NT   (KVLEN / AT_TK)    // 60
#define KTILE_F (AT_TK * KHS_STR)  // 4352 floats = 17408 B
#define VTILE_F (AT_TK * VHS_STR)  // 4608 floats = 18432 B
#define PS_STR  72
#define ATT_SMEM ((4 * KTILE_F + 4 * VTILE_F + 16 * 16 * PS_STR) * 4 + 64)

__global__ __launch_bounds__(512, 1)
void attn_mma(int dummy)
{
    extern __shared__ float sm[];
    float* Ks = sm;                              // [4][4352]
    float* Vs = sm + 4 * KTILE_F;                // [4][4608]
    float* Pa = sm + 4 * KTILE_F + 4 * VTILE_F;  // [16][16*72]
    const unsigned mb0 = smaddr(Pa + 16 * 16 * PS_STR);

    const int h   = blockIdx.x;
    const int qb  = blockIdx.y;
    const int tid = threadIdx.x;
    const int lane = tid & 31;
    const int w    = tid >> 5;
    const int grp  = lane >> 2;
    const int tig  = lane & 3;
    float* Pw = Pa + w * 16 * PS_STR;

    const float* ksrc = g_key_hs + (size_t)h * KHS_HEAD;
    const float* vsrc = g_val_hs + (size_t)h * VHS_HEAD;

    if (tid == 0) {
        mbar_init(mb0); mbar_init(mb0 + 8); mbar_init(mb0 + 16); mbar_init(mb0 + 24);
    }
    __syncthreads();
    if (tid == 0) {
#pragma unroll
        for (int s = 0; s < 4; s++) {
            mbar_expect(mb0 + 8 * s, 17408 + 18432);
            bulk_g2s(smaddr(Ks + s * KTILE_F), ksrc + (size_t)s * KTILE_F, 17408, mb0 + 8 * s);
            bulk_g2s(smaddr(Vs + s * VTILE_F), vsrc + (size_t)s * VTILE_F, 18432, mb0 + 8 * s);
        }
    }

    // Q fragments (pre-scaled tf32, log2 domain)
    unsigned qa[8][4];
    {
        const unsigned* q0 = g_query_t + (size_t)(qb * 256 + w * 16 + grp) * D_DIM + h * HDIM;
        const unsigned* q1 = q0 + 8 * D_DIM;
#pragma unroll
        for (int kb = 0; kb < 8; kb++) {
            qa[kb][0] = q0[kb * 8 + tig];
            qa[kb][1] = q1[kb * 8 + tig];
            qa[kb][2] = q0[kb * 8 + tig + 4];
            qa[kb][3] = q1[kb * 8 + tig + 4];
        }
    }

    float acc[8][4];
#pragma unroll
    for (int nt = 0; nt < 8; nt++)
#pragma unroll
        for (int i = 0; i < 4; i++) acc[nt][i] = 0.f;
    float m0 = -1e30f, m1 = -1e30f, l0 = 0.f, l1 = 0.f;

    for (int g = 0; g < AT_NT / 2; g++) {
#pragma unroll
        for (int sub = 0; sub < 2; sub++) {
            const int t = 2 * g + sub;
            const int s = t & 3;
            mbar_wait(mb0 + 8 * s, (unsigned)((t >> 2) & 1));

            const float* Kc = Ks + s * KTILE_F;
            const float* Vc = Vs + s * VTILE_F;

            // ---- S = Q K^T (log2 domain) ----
            float sc[8][4];
#pragma unroll
            for (int nt = 0; nt < 8; nt++)
#pragma unroll
                for (int i = 0; i < 4; i++) sc[nt][i] = 0.f;
#pragma unroll
            for (int kb = 0; kb < 8; kb++) {
#pragma unroll
                for (int nt = 0; nt < 8; nt++) {
                    unsigned b0 = __float_as_uint(Kc[(nt * 8 + grp) * KHS_STR + kb * 8 + tig]);
                    unsigned b1 = __float_as_uint(Kc[(nt * 8 + grp) * KHS_STR + kb * 8 + tig + 4]);
                    mma_tf32(sc[nt], qa[kb], b0, b1);
                }
            }

            // ---- online softmax (exp2) ----
            float mt0 = -1e30f, mt1 = -1e30f;
#pragma unroll
            for (int nt = 0; nt < 8; nt++) {
                mt0 = fmaxf(mt0, fmaxf(sc[nt][0], sc[nt][1]));
                mt1 = fmaxf(mt1, fmaxf(sc[nt][2], sc[nt][3]));
            }
            mt0 = fmaxf(mt0, __shfl_xor_sync(0xffffffff, mt0, 1));
            mt0 = fmaxf(mt0, __shfl_xor_sync(0xffffffff, mt0, 2));
            mt1 = fmaxf(mt1, __shfl_xor_sync(0xffffffff, mt1, 1));
            mt1 = fmaxf(mt1, __shfl_xor_sync(0xffffffff, mt1, 2));

            float mn0 = fmaxf(m0, mt0), mn1 = fmaxf(m1, mt1);
            float c0 = exp2f(m0 - mn0), c1 = exp2f(m1 - mn1);
            l0 *= c0; l1 *= c1;
            m0 = mn0; m1 = mn1;

#pragma unroll
            for (int nt = 0; nt < 8; nt++) {
                float p00 = exp2f(sc[nt][0] - mn0);
                float p01 = exp2f(sc[nt][1] - mn0);
                float p10 = exp2f(sc[nt][2] - mn1);
                float p11 = exp2f(sc[nt][3] - mn1);
                l0 += p00 + p01;
                l1 += p10 + p11;
                *(float2*)&Pw[grp * PS_STR + nt * 8 + 2 * tig]       = make_float2(p00, p01);
                *(float2*)&Pw[(grp + 8) * PS_STR + nt * 8 + 2 * tig] = make_float2(p10, p11);
                acc[nt][0] *= c0; acc[nt][1] *= c0;
                acc[nt][2] *= c1; acc[nt][3] *= c1;
            }
            __syncwarp();

            // ---- acc += P @ V ----
#pragma unroll
            for (int kb = 0; kb < 8; kb++) {
                unsigned a[4];
                a[0] = __float_as_uint(Pw[grp * PS_STR + kb * 8 + tig]);
                a[1] = __float_as_uint(Pw[(grp + 8) * PS_STR + kb * 8 + tig]);
                a[2] = __float_as_uint(Pw[grp * PS_STR + kb * 8 + tig + 4]);
                a[3] = __float_as_uint(Pw[(grp + 8) * PS_STR + kb * 8 + tig + 4]);
#pragma unroll
                for (int nt = 0; nt < 8; nt++) {
                    unsigned b0 = __float_as_uint(Vc[(kb * 8 + tig) * VHS_STR + nt * 8 + grp]);
                    unsigned b1 = __float_as_uint(Vc[(kb * 8 + tig + 4) * VHS_STR + nt * 8 + grp]);
                    mma_tf32(acc[nt], a, b0, b1);
                }
            }
        }

        __syncthreads();
        if (tid == 0 && 2 * g + 4 < AT_NT) {
#pragma unroll
            for (int sub = 0; sub < 2; sub++) {
                const int t = 2 * g + 4 + sub;
                const int s = t & 3;
                mbar_expect(mb0 + 8 * s, 17408 + 18432);
                bulk_g2s(smaddr(Ks + s * KTILE_F), ksrc + (size_t)t * KTILE_F, 17408, mb0 + 8 * s);
                bulk_g2s(smaddr(Vs + s * VTILE_F), vsrc + (size_t)t * VTILE_F, 18432, mb0 + 8 * s);
            }
        }
    }

    // ---- finalize: write blocked layout for gemm2 ----
    l0 += __shfl_xor_sync(0xffffffff, l0, 1);
    l0 += __shfl_xor_sync(0xffffffff, l0, 2);
    l1 += __shfl_xor_sync(0xffffffff, l1, 1);
    l1 += __shfl_xor_sync(0xffffffff, l1, 2);
    float inv0 = 1.f / l0, inv1 = 1.f / l1;

    int r0 = qb * 256 + w * 16 + grp;
    int r1 = r0 + 8;
#pragma unroll
    for (int nt = 0; nt < 8; nt++) {
        int col = h * HDIM + nt * 8 + 2 * tig;
        int kt = col >> 4, c = col & 15;
        size_t o0 = ((size_t)(r0 >> 7) * 64 + kt) * BLKW + (r0 & 127) * 20 + c;
        size_t o1 = ((size_t)(r1 >> 7) * 64 + kt) * BLKW + (r1 & 127) * 20 + c;
        *(uint2*)(g_attn_blk + o0) = make_uint2(f2tf32(acc[nt][0] * inv0), f2tf32(acc[nt][1] * inv0));
        *(uint2*)(g_attn_blk + o1) = make_uint2(f2tf32(acc[nt][2] * inv1), f2tf32(acc[nt][3] * inv1));
    }
}

// ---------------------------------------------------------------------------
extern "C" void kernel_launch(void* const* d_in, const int* in_sizes, int n_in,
                              void* d_out, int out_size)
{
    const float* utter = (const float*)d_in[0];
    const float* rctx  = (const float*)d_in[1];
    const float* mem   = (const float*)d_in[2];
    const float* lck   = (const float*)d_in[3];
    const float* lcv   = (const float*)d_in[4];
    const float* Wq    = (const float*)d_in[5];
    const float* bq    = (const float*)d_in[6];
    const float* Wkv   = (const float*)d_in[7];
    const float* bkv   = (const float*)d_in[8];
    const float* Wo    = (const float*)d_in[9];
    const float* bo    = (const float*)d_in[10];

    float* out = (float*)d_out;                       // [2304, 1024]
    float* key = out + (size_t)QLEN * D_DIM;          // [3840, 1024]
    float* val = key + (size_t)KVLEN * D_DIM;         // [3840, 1024]

    static bool attr_done = false;
    if (!attr_done) {
        cudaFuncSetAttribute(attn_mma, cudaFuncAttributeMaxDynamicSharedMemorySize, ATT_SMEM);
        cudaFuncSetAttribute(gemm_blk<0>, cudaFuncAttributeMaxDynamicSharedMemorySize, GEMM_SMEM);
        cudaFuncSetAttribute(gemm_blk<1>, cudaFuncAttributeMaxDynamicSharedMemorySize, GEMM_SMEM);
        cudaFuncSetAttribute(gemm_blk<2>, cudaFuncAttributeMaxDynamicSharedMemorySize, GEMM_SMEM);
        attr_done = true;
    }

    unsigned *wq_b, *wkv_b, *wo_b;
    cudaGetSymbolAddress((void**)&wq_b,  g_Wq_blk);
    cudaGetSymbolAddress((void**)&wkv_b, g_Wkv_blk);
    cudaGetSymbolAddress((void**)&wo_b,  g_Wo_blk);

    // 0) prepass conversions
    conv_w_blk<<<256, 256>>>(Wq,  wq_b,  D_DIM * D_DIM / 4);
    conv_w_blk<<<512, 256>>>(Wkv, wkv_b, 2 * D_DIM * D_DIM / 4);
    conv_w_blk<<<256, 256>>>(Wo,  wo_b,  D_DIM * D_DIM / 4);
    conv_kvin_blk<<<512, 256>>>(utter, rctx, mem);
    conv_lc<<<256, 256>>>(lck, lcv);

    // 1) query projection -> g_query_t (pre-scaled tf32, log2 domain)
    gemm_blk<0><<<dim3(D_DIM / 128, QLEN / 128), 256, GEMM_SMEM>>>(bq, nullptr, nullptr);

    // 2) kv projection -> key/value (fp32) + head-major padded copies
    gemm_blk<1><<<dim3(2 * D_DIM / 128, KVIN / 128), 256, GEMM_SMEM>>>(bkv, key, val);

    // 3) left-context splice into d_out (contiguous)
    cudaMemcpyAsync(key + (size_t)MR * D_DIM, lck,
                    (size_t)L_LEN * D_DIM * sizeof(float),
                    cudaMemcpyDeviceToDevice, 0);
    cudaMemcpyAsync(val + (size_t)MR * D_DIM, lcv,
                    (size_t)L_LEN * D_DIM * sizeof(float),
                    cudaMemcpyDeviceToDevice, 0);

    // 4) attention -> g_attn_blk (blocked tf32)
    attn_mma<<<dim3(NHEAD, QLEN / 256), 512, ATT_SMEM>>>(0);

    // 5) output projection
    gemm_blk<2><<<dim3(D_DIM / 128, QLEN / 128), 256, GEMM_SMEM>>>(bo, out, nullptr);
}

// round 10
// speedup vs baseline: 1.2214x; 1.0041x over previous
#include <cuda_runtime.h>

// Problem dims
#define U_LEN 2048
#define R_LEN 256
#define L_LEN 1024
#define M_LEN 512
#define D_DIM 1024
#define NHEAD 16
#define HDIM  64
#define QLEN  (U_LEN + R_LEN)                   // 2304
#define KVLEN (M_LEN + R_LEN + L_LEN + U_LEN)   // 3840
#define MR    (M_LEN + R_LEN)                   // 768
#define KVIN  (MR + U_LEN)                      // 2816

// A tile: 128 rows x 16 k (+4 pad) = 2560 words = 10240 B (unchanged R8)
#define BLKW   2560
#define TILEB  10240
// B tile: 128 rows x 16 k pair-packed, stride 24 -> 3072 words = 12288 B
#define BTW    3072
#define BTILEB 12288
#define NKT    (D_DIM / 16)      // 64 k-tiles

// head-major K: row stride 72 words, col pairs (c,c+4) packed
// head-major V: per 64-row tile, column-major: c*72 + rowpair*2 + half
#define KV_STR  72
#define KTILE_F (64 * KV_STR)        // 4608
#define VTILE_F (64 * KV_STR)        // 4608
#define KHEAD_W (KVLEN * KV_STR)     // 276480
#define VHEAD_W (KVLEN * KV_STR)     // 276480

// log2(e) folded into q scaling: scores arrive in log2 domain
#define QSCALE (0.125f * 1.4426950408889634f)

// Scratch (no cudaMalloc allowed)
__device__ unsigned g_kvin_blk[22 * 64 * BLKW];
__device__ unsigned g_attn_blk[18 * 64 * BLKW];
__device__ unsigned g_Wq_blk  [ 8 * 64 * BTW];
__device__ unsigned g_Wkv_blk [16 * 64 * BTW];
__device__ unsigned g_Wo_blk  [ 8 * 64 * BTW];
__device__ unsigned g_query_t [QLEN * D_DIM];        // pre-scaled tf32 query
__device__ float    g_key_hs  [NHEAD * KHEAD_W];
__device__ float    g_val_hs  [NHEAD * VHEAD_W];

// ---------------------------------------------------------------------------
// helpers
// ---------------------------------------------------------------------------
__device__ __forceinline__ unsigned f2tf32(float f) {
    unsigned r;
    asm("cvt.rna.tf32.f32 %0, %1;" : "=r"(r) : "f"(f));
    return r;
}

__device__ __forceinline__ void mma_tf32(float* d, const unsigned* a, unsigned b0, unsigned b1) {
    asm volatile(
        "mma.sync.aligned.m16n8k8.row.col.f32.tf32.tf32.f32 "
        "{%0,%1,%2,%3}, {%4,%5,%6,%7}, {%8,%9}, {%0,%1,%2,%3};"
        : "+f"(d[0]), "+f"(d[1]), "+f"(d[2]), "+f"(d[3])
        : "r"(a[0]), "r"(a[1]), "r"(a[2]), "r"(a[3]), "r"(b0), "r"(b1));
}

__device__ __forceinline__ unsigned smaddr(const void* p) {
    return (unsigned)__cvta_generic_to_shared(p);
}
__device__ __forceinline__ void mbar_init(unsigned a) {
    asm volatile("mbarrier.init.shared.b64 [%0], 1;" :: "r"(a) : "memory");
}
__device__ __forceinline__ void mbar_expect(unsigned a, unsigned tx) {
    asm volatile("mbarrier.arrive.expect_tx.shared.b64 _, [%0], %1;" :: "r"(a), "r"(tx) : "memory");
}
__device__ __forceinline__ void bulk_g2s(unsigned sdst, const void* gsrc, unsigned bytes, unsigned mbar) {
    asm volatile("cp.async.bulk.shared::cta.global.mbarrier::complete_tx::bytes [%0], [%1], %2, [%3];"
                 :: "r"(sdst), "l"(gsrc), "r"(bytes), "r"(mbar) : "memory");
}
__device__ __forceinline__ void mbar_wait(unsigned a, unsigned ph) {
    asm volatile(
        "{\n\t.reg .pred P;\n\t"
        "WL%=:\n\t"
        "mbarrier.try_wait.parity.acquire.cta.shared::cta.b64 P, [%0], %1, 0x989680;\n\t"
        "@P bra WD%=;\n\t"
        "bra WL%=;\n\t"
        "WD%=:\n\t}"
        :: "r"(a), "r"(ph) : "memory");
}

// pair-pack index helpers: pair p holds (c, c+4); p = (c>>3)*4 + (c&3), q = (c>>2)&1
__device__ __forceinline__ int pk_p(int c) { return ((c >> 3) << 2) + (c & 3); }
__device__ __forceinline__ int pk_q(int c) { return (c >> 2) & 1; }
// V rowpair: rp holds (j, j+4); rp = (j>>3)*4 + (j&3), h = (j>>2)&1
__device__ __forceinline__ int v_rp(int j) { return ((j >> 3) << 2) + (j & 3); }
__device__ __forceinline__ int v_h(int j)  { return (j >> 2) & 1; }

// ---------------------------------------------------------------------------
// Prepass: weights -> pair-packed B tiles (stride 24)
// ---------------------------------------------------------------------------
__global__ void conv_w_blk(const float* __restrict__ src, unsigned* __restrict__ dst, int n4)
{
    int i = blockIdx.x * blockDim.x + threadIdx.x;
    for (; i < n4; i += gridDim.x * blockDim.x) {
        int row = i >> 8;
        int col = (i & 255) * 4;
        float4 v = ((const float4*)src)[i];
        int c0 = col & 15;                         // 0,4,8,12
        int q = pk_q(c0);
        int p0 = (c0 >> 3) * 4;                    // c&3 runs 0..3
        unsigned* base = dst + ((size_t)((row >> 7) * 64 + (col >> 4))) * BTW
                       + (row & 127) * 24 + q;
        base[(p0 + 0) * 2] = f2tf32(v.x);
        base[(p0 + 1) * 2] = f2tf32(v.y);
        base[(p0 + 2) * 2] = f2tf32(v.z);
        base[(p0 + 3) * 2] = f2tf32(v.w);
    }
}

// Prepass: gather concat(mem, rctx, utter) -> blocked A tiles (unchanged layout)
__global__ void conv_kvin_blk(const float* __restrict__ utter,
                              const float* __restrict__ rctx,
                              const float* __restrict__ mem)
{
    int i = blockIdx.x * blockDim.x + threadIdx.x;
    const int n4 = KVIN * D_DIM / 4;
    for (; i < n4; i += gridDim.x * blockDim.x) {
        int row = i >> 8;
        int col = (i & 255) * 4;
        const float4* s = (row < M_LEN)
            ? (const float4*)(mem + (size_t)row * D_DIM + col)
            : (row < MR)
            ? (const float4*)(rctx + (size_t)(row - M_LEN) * D_DIM + col)
            : (const float4*)(utter + (size_t)(row - MR) * D_DIM + col);
        float4 v = *s;
        uint4 o;
        o.x = f2tf32(v.x); o.y = f2tf32(v.y); o.z = f2tf32(v.z); o.w = f2tf32(v.w);
        size_t off = ((size_t)(row >> 7) * 64 + (col >> 4)) * BLKW + (row & 127) * 20 + (col & 15);
        *(uint4*)(g_kvin_blk + off) = o;
    }
}

// Prepass: left-context rows into packed head-major K/V
__global__ void conv_lc(const float* __restrict__ lck, const float* __restrict__ lcv)
{
    int i = blockIdx.x * blockDim.x + threadIdx.x;
    const int n4 = L_LEN * D_DIM / 4;
    for (; i < n4; i += gridDim.x * blockDim.x) {
        int row = i >> 8;
        int col = (i & 255) * 4;
        int head = col >> 6, c0 = col & 63;        // c0 in {0,4,...,60}
        int krow = MR + row;
        float4 k4 = *(const float4*)(lck + (size_t)row * D_DIM + col);
        float4 v4 = *(const float4*)(lcv + (size_t)row * D_DIM + col);
        // K: row-major stride 72, pair-packed columns
        {
            int q = pk_q(c0);
            int p0 = (c0 >> 3) * 4;
            float* base = g_key_hs + (size_t)head * KHEAD_W + (size_t)krow * KV_STR + q;
            base[(p0 + 0) * 2] = k4.x;
            base[(p0 + 1) * 2] = k4.y;
            base[(p0 + 2) * 2] = k4.z;
            base[(p0 + 3) * 2] = k4.w;
        }
        // V: per 64-row tile, column-major (c*72 + rp*2 + h)
        {
            int tile = krow >> 6, j = krow & 63;
            float* base = g_val_hs + (size_t)head * VHEAD_W + (size_t)tile * VTILE_F
                        + v_rp(j) * 2 + v_h(j);
            base[(c0 + 0) * KV_STR] = v4.x;
            base[(c0 + 1) * KV_STR] = v4.y;
            base[(c0 + 2) * KV_STR] = v4.z;
            base[(c0 + 3) * KV_STR] = v4.w;
        }
    }
}

// ---------------------------------------------------------------------------
// TF32 GEMM with bulk-copy pipeline: C = A_blk @ W_blk^T + bias
// BM=BN=128, BK=16, 256 threads (8 warps 4x2), 4-stage, sync per 2 k-tiles.
// B fragments are single LDS.64 (pair-packed, conflict-free).
// ---------------------------------------------------------------------------
#define GEMM_SMEM ((4 * BLKW + 4 * BTW) * 4 + 64)

template <int MODE>
__global__ __launch_bounds__(256, 2)
void gemm_blk(const float* __restrict__ bias,
              float* __restrict__ C0,
              float* __restrict__ C1)
{
    extern __shared__ unsigned gsm[];
    unsigned* As = gsm;               // [4][2560]
    unsigned* Bs = gsm + 4 * BLKW;    // [4][3072]
    const unsigned mb0 = smaddr(gsm + 4 * BLKW + 4 * BTW);

    const int tid  = threadIdx.x;
    const int lane = tid & 31;
    const int warp = tid >> 5;
    const int wr   = warp & 3;
    const int wc   = warp >> 2;
    const int bm = blockIdx.y, bn = blockIdx.x;
    const int tig = lane & 3, grp = lane >> 2;

    const unsigned* Ab =
        (MODE == 0) ? g_kvin_blk + (size_t)(bm + 4) * 64 * BLKW
      : (MODE == 1) ? g_kvin_blk + (size_t)bm * 64 * BLKW
                    : g_attn_blk + (size_t)bm * 64 * BLKW;
    const unsigned* Wb =
        ((MODE == 0) ? g_Wq_blk : (MODE == 1) ? g_Wkv_blk : g_Wo_blk)
        + (size_t)bn * 64 * BTW;

    if (tid == 0) {
        mbar_init(mb0); mbar_init(mb0 + 8); mbar_init(mb0 + 16); mbar_init(mb0 + 24);
    }
    __syncthreads();
    if (tid == 0) {
#pragma unroll
        for (int s = 0; s < 4; s++) {
            mbar_expect(mb0 + 8 * s, TILEB + BTILEB);
            bulk_g2s(smaddr(As + s * BLKW), Ab + (size_t)s * BLKW, TILEB, mb0 + 8 * s);
            bulk_g2s(smaddr(Bs + s * BTW),  Wb + (size_t)s * BTW,  BTILEB, mb0 + 8 * s);
        }
    }

    float acc[2][8][4];
#pragma unroll
    for (int mt = 0; mt < 2; mt++)
#pragma unroll
        for (int nt = 0; nt < 8; nt++)
#pragma unroll
            for (int i = 0; i < 4; i++) acc[mt][nt][i] = 0.f;

    for (int g = 0; g < NKT / 2; g++) {
#pragma unroll
        for (int sub = 0; sub < 2; sub++) {
            const int kt = 2 * g + sub;
            const int s  = kt & 3;
            mbar_wait(mb0 + 8 * s, (unsigned)((kt >> 2) & 1));

            const unsigned* Asl = As + s * BLKW;
            const unsigned* Bsl = Bs + s * BTW;
#pragma unroll
            for (int ks = 0; ks < 2; ks++) {
                int kk = ks * 8;
                unsigned b[8][2];
#pragma unroll
                for (int nt = 0; nt < 8; nt++) {
                    int brow = wc * 64 + nt * 8 + grp;
                    uint2 bb = *(const uint2*)(Bsl + brow * 24 + (ks * 4 + tig) * 2);
                    b[nt][0] = bb.x; b[nt][1] = bb.y;
                }
#pragma unroll
                for (int mt = 0; mt < 2; mt++) {
                    unsigned a[4];
                    int r0 = wr * 32 + mt * 16 + grp;
                    a[0] = Asl[r0 * 20 + kk + tig];       a[1] = Asl[(r0 + 8) * 20 + kk + tig];
                    a[2] = Asl[r0 * 20 + kk + tig + 4];   a[3] = Asl[(r0 + 8) * 20 + kk + tig + 4];
#pragma unroll
                    for (int nt = 0; nt < 8; nt++) mma_tf32(acc[mt][nt], a, b[nt][0], b[nt][1]);
                }
            }
        }
        __syncthreads();
        if (tid == 0 && 2 * g + 4 < NKT) {
#pragma unroll
            for (int sub = 0; sub < 2; sub++) {
                const int kt = 2 * g + 4 + sub;
                const int s  = kt & 3;
                mbar_expect(mb0 + 8 * s, TILEB + BTILEB);
                bulk_g2s(smaddr(As + s * BLKW), Ab + (size_t)kt * BLKW, TILEB, mb0 + 8 * s);
                bulk_g2s(smaddr(Bs + s * BTW),  Wb + (size_t)kt * BTW,  BTILEB, mb0 + 8 * s);
            }
        }
    }

    // epilogue
#pragma unroll
    for (int mt = 0; mt < 2; mt++) {
#pragma unroll
        for (int nt = 0; nt < 8; nt++) {
            int col = bn * 128 + wc * 64 + nt * 8 + 2 * tig;
#pragma unroll
            for (int half = 0; half < 2; half++) {
                int row = bm * 128 + wr * 32 + mt * 16 + grp + half * 8;
                float v0 = acc[mt][nt][half * 2 + 0] + bias[col];
                float v1 = acc[mt][nt][half * 2 + 1] + bias[col + 1];
                if (MODE == 0) {
                    uint2 o = make_uint2(f2tf32(v0 * QSCALE), f2tf32(v1 * QSCALE));
                    *(uint2*)(g_query_t + (size_t)row * D_DIM + col) = o;
                } else if (MODE == 1) {
                    int krow = (row < MR) ? row : row + L_LEN;
                    if (col < D_DIM) {
                        *(float2*)(C0 + (size_t)krow * D_DIM + col) = make_float2(v0, v1);
                        int head = col >> 6, c = col & 63;
                        float* base = g_key_hs + (size_t)head * KHEAD_W
                                    + (size_t)krow * KV_STR + pk_q(c);
                        int p = pk_p(c);
                        base[p * 2] = v0;
                        base[p * 2 + 2] = v1;       // pk_p(c+1) = p+1 (c even)
                    } else {
                        int vc = col - D_DIM;
                        *(float2*)(C1 + (size_t)krow * D_DIM + vc) = make_float2(v0, v1);
                        int head = vc >> 6, c = vc & 63;
                        int tile = krow >> 6, j = krow & 63;
                        float* base = g_val_hs + (size_t)head * VHEAD_W + (size_t)tile * VTILE_F
                                    + v_rp(j) * 2 + v_h(j);
                        base[c * KV_STR] = v0;
                        base[(c + 1) * KV_STR] = v1;
                    }
                } else {
                    *(float2*)(C0 + (size_t)row * D_DIM + col) = make_float2(v0, v1);
                }
            }
        }
    }
}

// ---------------------------------------------------------------------------
// Tensor-core flash attention, 512 threads = 256 q rows of one head.
// 4-stage bulk pipeline, sync per 2 tiles. K/V fragments single LDS.64.
// Softmax in log2 domain.
// ---------------------------------------------------------------------------
#define AT_TK   64
#define AT_NT   (KVLEN / AT_TK)    // 60
#define PS_STR  72
#define ATT_SMEM ((4 * KTILE_F + 4 * VTILE_F + 16 * 16 * PS_STR) * 4 + 64)

__global__ __launch_bounds__(512, 1)
void attn_mma(int dummy)
{
    extern __shared__ float sm[];
    float* Ks = sm;                              // [4][4608]
    float* Vs = sm + 4 * KTILE_F;                // [4][4608]
    float* Pa = sm + 4 * KTILE_F + 4 * VTILE_F;  // [16][16*72]
    const unsigned mb0 = smaddr(Pa + 16 * 16 * PS_STR);

    const int h   = blockIdx.x;
    const int qb  = blockIdx.y;
    const int tid = threadIdx.x;
    const int lane = tid & 31;
    const int w    = tid >> 5;
    const int grp  = lane >> 2;
    const int tig  = lane & 3;
    float* Pw = Pa + w * 16 * PS_STR;

    const float* ksrc = g_key_hs + (size_t)h * KHEAD_W;
    const float* vsrc = g_val_hs + (size_t)h * VHEAD_W;

    if (tid == 0) {
        mbar_init(mb0); mbar_init(mb0 + 8); mbar_init(mb0 + 16); mbar_init(mb0 + 24);
    }
    __syncthreads();
    if (tid == 0) {
#pragma unroll
        for (int s = 0; s < 4; s++) {
            mbar_expect(mb0 + 8 * s, (KTILE_F + VTILE_F) * 4);
            bulk_g2s(smaddr(Ks + s * KTILE_F), ksrc + (size_t)s * KTILE_F, KTILE_F * 4, mb0 + 8 * s);
            bulk_g2s(smaddr(Vs + s * VTILE_F), vsrc + (size_t)s * VTILE_F, VTILE_F * 4, mb0 + 8 * s);
        }
    }

    // Q fragments (pre-scaled tf32, log2 domain)
    unsigned qa[8][4];
    {
        const unsigned* q0 = g_query_t + (size_t)(qb * 256 + w * 16 + grp) * D_DIM + h * HDIM;
        const unsigned* q1 = q0 + 8 * D_DIM;
#pragma unroll
        for (int kb = 0; kb < 8; kb++) {
            qa[kb][0] = q0[kb * 8 + tig];
            qa[kb][1] = q1[kb * 8 + tig];
            qa[kb][2] = q0[kb * 8 + tig + 4];
            qa[kb][3] = q1[kb * 8 + tig + 4];
        }
    }

    float acc[8][4];
#pragma unroll
    for (int nt = 0; nt < 8; nt++)
#pragma unroll
        for (int i = 0; i < 4; i++) acc[nt][i] = 0.f;
    float m0 = -1e30f, m1 = -1e30f, l0 = 0.f, l1 = 0.f;

    for (int g = 0; g < AT_NT / 2; g++) {
#pragma unroll
        for (int sub = 0; sub < 2; sub++) {
            const int t = 2 * g + sub;
            const int s = t & 3;
            mbar_wait(mb0 + 8 * s, (unsigned)((t >> 2) & 1));

            const float* Kc = Ks + s * KTILE_F;
            const float* Vc = Vs + s * VTILE_F;

            // ---- S = Q K^T (log2 domain); K b-frag = 1 LDS.64 ----
            float sc[8][4];
#pragma unroll
            for (int nt = 0; nt < 8; nt++)
#pragma unroll
                for (int i = 0; i < 4; i++) sc[nt][i] = 0.f;
#pragma unroll
            for (int kb = 0; kb < 8; kb++) {
#pragma unroll
                for (int nt = 0; nt < 8; nt++) {
                    uint2 bb = *(const uint2*)(Kc + (nt * 8 + grp) * KV_STR + (kb * 4 + tig) * 2);
                    mma_tf32(sc[nt], qa[kb], bb.x, bb.y);
                }
            }

            // ---- online softmax (exp2) ----
            float mt0 = -1e30f, mt1 = -1e30f;
#pragma unroll
            for (int nt = 0; nt < 8; nt++) {
                mt0 = fmaxf(mt0, fmaxf(sc[nt][0], sc[nt][1]));
                mt1 = fmaxf(mt1, fmaxf(sc[nt][2], sc[nt][3]));
            }
            mt0 = fmaxf(mt0, __shfl_xor_sync(0xffffffff, mt0, 1));
            mt0 = fmaxf(mt0, __shfl_xor_sync(0xffffffff, mt0, 2));
            mt1 = fmaxf(mt1, __shfl_xor_sync(0xffffffff, mt1, 1));
            mt1 = fmaxf(mt1, __shfl_xor_sync(0xffffffff, mt1, 2));

            float mn0 = fmaxf(m0, mt0), mn1 = fmaxf(m1, mt1);
            float c0 = exp2f(m0 - mn0), c1 = exp2f(m1 - mn1);
            l0 *= c0; l1 *= c1;
            m0 = mn0; m1 = mn1;

#pragma unroll
            for (int nt = 0; nt < 8; nt++) {
                float p00 = exp2f(sc[nt][0] - mn0);
                float p01 = exp2f(sc[nt][1] - mn0);
                float p10 = exp2f(sc[nt][2] - mn1);
                float p11 = exp2f(sc[nt][3] - mn1);
                l0 += p00 + p01;
                l1 += p10 + p11;
                *(float2*)&Pw[grp * PS_STR + nt * 8 + 2 * tig]       = make_float2(p00, p01);
                *(float2*)&Pw[(grp + 8) * PS_STR + nt * 8 + 2 * tig] = make_float2(p10, p11);
                acc[nt][0] *= c0; acc[nt][1] *= c0;
                acc[nt][2] *= c1; acc[nt][3] *= c1;
            }
            __syncwarp();

            // ---- acc += P @ V ; V b-frag = 1 LDS.64 ----
#pragma unroll
            for (int kb = 0; kb < 8; kb++) {
                unsigned a[4];
                a[0] = __float_as_uint(Pw[grp * PS_STR + kb * 8 + tig]);
                a[1] = __float_as_uint(Pw[(grp + 8) * PS_STR + kb * 8 + tig]);
                a[2] = __float_as_uint(Pw[grp * PS_STR + kb * 8 + tig + 4]);
                a[3] = __float_as_uint(Pw[(grp + 8) * PS_STR + kb * 8 + tig + 4]);
#pragma unroll
                for (int nt = 0; nt < 8; nt++) {
                    uint2 bb = *(const uint2*)(Vc + (nt * 8 + grp) * KV_STR + (kb * 4 + tig) * 2);
                    mma_tf32(acc[nt], a, bb.x, bb.y);
                }
            }
        }

        __syncthreads();
        if (tid == 0 && 2 * g + 4 < AT_NT) {
#pragma unroll
            for (int sub = 0; sub < 2; sub++) {
                const int t = 2 * g + 4 + sub;
                const int s = t & 3;
                mbar_expect(mb0 + 8 * s, (KTILE_F + VTILE_F) * 4);
                bulk_g2s(smaddr(Ks + s * KTILE_F), ksrc + (size_t)t * KTILE_F, KTILE_F * 4, mb0 + 8 * s);
                bulk_g2s(smaddr(Vs + s * VTILE_F), vsrc + (size_t)t * VTILE_F, VTILE_F * 4, mb0 + 8 * s);
            }
        }
    }

    // ---- finalize: write blocked A layout for gemm2 ----
    l0 += __shfl_xor_sync(0xffffffff, l0, 1);
    l0 += __shfl_xor_sync(0xffffffff, l0, 2);
    l1 += __shfl_xor_sync(0xffffffff, l1, 1);
    l1 += __shfl_xor_sync(0xffffffff, l1, 2);
    float inv0 = 1.f / l0, inv1 = 1.f / l1;

    int r0 = qb * 256 + w * 16 + grp;
    int r1 = r0 + 8;
#pragma unroll
    for (int nt = 0; nt < 8; nt++) {
        int col = h * HDIM + nt * 8 + 2 * tig;
        int kt = col >> 4, c = col & 15;
        size_t o0 = ((size_t)(r0 >> 7) * 64 + kt) * BLKW + (r0 & 127) * 20 + c;
        size_t o1 = ((size_t)(r1 >> 7) * 64 + kt) * BLKW + (r1 & 127) * 20 + c;
        *(uint2*)(g_attn_blk + o0) = make_uint2(f2tf32(acc[nt][0] * inv0), f2tf32(acc[nt][1] * inv0));
        *(uint2*)(g_attn_blk + o1) = make_uint2(f2tf32(acc[nt][2] * inv1), f2tf32(acc[nt][3] * inv1));
    }
}

// ---------------------------------------------------------------------------
extern "C" void kernel_launch(void* const* d_in, const int* in_sizes, int n_in,
                              void* d_out, int out_size)
{
    const float* utter = (const float*)d_in[0];
    const float* rctx  = (const float*)d_in[1];
    const float* mem   = (const float*)d_in[2];
    const float* lck   = (const float*)d_in[3];
    const float* lcv   = (const float*)d_in[4];
    const float* Wq    = (const float*)d_in[5];
    const float* bq    = (const float*)d_in[6];
    const float* Wkv   = (const float*)d_in[7];
    const float* bkv   = (const float*)d_in[8];
    const float* Wo    = (const float*)d_in[9];
    const float* bo    = (const float*)d_in[10];

    float* out = (float*)d_out;                       // [2304, 1024]
    float* key = out + (size_t)QLEN * D_DIM;          // [3840, 1024]
    float* val = key + (size_t)KVLEN * D_DIM;         // [3840, 1024]

    static bool attr_done = false;
    if (!attr_done) {
        cudaFuncSetAttribute(attn_mma, cudaFuncAttributeMaxDynamicSharedMemorySize, ATT_SMEM);
        cudaFuncSetAttribute(gemm_blk<0>, cudaFuncAttributeMaxDynamicSharedMemorySize, GEMM_SMEM);
        cudaFuncSetAttribute(gemm_blk<1>, cudaFuncAttributeMaxDynamicSharedMemorySize, GEMM_SMEM);
        cudaFuncSetAttribute(gemm_blk<2>, cudaFuncAttributeMaxDynamicSharedMemorySize, GEMM_SMEM);
        attr_done = true;
    }

    unsigned *wq_b, *wkv_b, *wo_b;
    cudaGetSymbolAddress((void**)&wq_b,  g_Wq_blk);
    cudaGetSymbolAddress((void**)&wkv_b, g_Wkv_blk);
    cudaGetSymbolAddress((void**)&wo_b,  g_Wo_blk);

    // 0) prepass conversions
    conv_w_blk<<<256, 256>>>(Wq,  wq_b,  D_DIM * D_DIM / 4);
    conv_w_blk<<<512, 256>>>(Wkv, wkv_b, 2 * D_DIM * D_DIM / 4);
    conv_w_blk<<<256, 256>>>(Wo,  wo_b,  D_DIM * D_DIM / 4);
    conv_kvin_blk<<<512, 256>>>(utter, rctx, mem);
    conv_lc<<<256, 256>>>(lck, lcv);

    // 1) query projection -> g_query_t (pre-scaled tf32, log2 domain)
    gemm_blk<0><<<dim3(D_DIM / 128, QLEN / 128), 256, GEMM_SMEM>>>(bq, nullptr, nullptr);

    // 2) kv projection -> key/value (fp32) + packed head-major copies
    gemm_blk<1><<<dim3(2 * D_DIM / 128, KVIN / 128), 256, GEMM_SMEM>>>(bkv, key, val);

    // 3) left-context splice into d_out (contiguous)
    cudaMemcpyAsync(key + (size_t)MR * D_DIM, lck,
                    (size_t)L_LEN * D_DIM * sizeof(float),
                    cudaMemcpyDeviceToDevice, 0);
    cudaMemcpyAsync(val + (size_t)MR * D_DIM, lcv,
                    (size_t)L_LEN * D_DIM * sizeof(float),
                    cudaMemcpyDeviceToDevice, 0);

    // 4) attention -> g_attn_blk (blocked tf32)
    attn_mma<<<dim3(NHEAD, QLEN / 256), 512, ATT_SMEM>>>(0);

    // 5) output projection
    gemm_blk<2><<<dim3(D_DIM / 128, QLEN / 128), 256, GEMM_SMEM>>>(bo, out, nullptr);
}